// round 14
// baseline (speedup 1.0000x reference)
#include <cuda_runtime.h>
#include <cuda_fp16.h>
#include <math.h>

#define Bsz 4
#define Tseq 2048
#define Emb 1024
#define HQ 16
#define HKV 4
#define HD 64
#define TOTQ (HQ*HD)            // 1024
#define TOTKV (HKV*HD)          // 256
#define Fqkv (TOTQ + 2*TOTKV)   // 1536
#define Mrows (Bsz*Tseq)        // 8192
#define QSCALE 0.1803368801111204f   // 0.125 * log2(e)

// Scratch (no allocations allowed -> __device__ globals)
__device__ __half g_xh[Mrows*Emb];
__device__ __half g_wqkvh[Fqkv*Emb];
__device__ __half g_wouth[TOTQ*Emb];
__device__ __half g_qh[Bsz*HQ*Tseq*HD];
__device__ __half g_kh[Bsz*HKV*Tseq*HD];
__device__ __half g_vh[Bsz*HKV*Tseq*HD];
__device__ __half g_attnh[Mrows * TOTQ];
__device__ float  g_cos[Tseq*32];
__device__ float  g_sin[Tseq*32];

// ---------------------------------------------------------------------------
// helpers
// ---------------------------------------------------------------------------
__device__ __forceinline__ void mma_f16(float* c, const unsigned* a,
                                        unsigned b0, unsigned b1) {
    asm volatile(
        "mma.sync.aligned.m16n8k16.row.col.f32.f16.f16.f32 "
        "{%0,%1,%2,%3}, {%4,%5,%6,%7}, {%8,%9}, {%0,%1,%2,%3};"
        : "+f"(c[0]), "+f"(c[1]), "+f"(c[2]), "+f"(c[3])
        : "r"(a[0]), "r"(a[1]), "r"(a[2]), "r"(a[3]), "r"(b0), "r"(b1));
}

__device__ __forceinline__ void ldsm_x4(unsigned* r, const void* p) {
    unsigned addr = (unsigned)__cvta_generic_to_shared(p);
    asm volatile("ldmatrix.sync.aligned.m8n8.x4.shared.b16 {%0,%1,%2,%3}, [%4];"
        : "=r"(r[0]), "=r"(r[1]), "=r"(r[2]), "=r"(r[3]) : "r"(addr));
}

__device__ __forceinline__ void ldsm_x4_t(unsigned* r, const void* p) {
    unsigned addr = (unsigned)__cvta_generic_to_shared(p);
    asm volatile("ldmatrix.sync.aligned.m8n8.x4.trans.shared.b16 {%0,%1,%2,%3}, [%4];"
        : "=r"(r[0]), "=r"(r[1]), "=r"(r[2]), "=r"(r[3]) : "r"(addr));
}

__device__ __forceinline__ void cp16(void* s, const void* g) {
    unsigned sa = (unsigned)__cvta_generic_to_shared(s);
    asm volatile("cp.async.cg.shared.global [%0], [%1], 16;" :: "r"(sa), "l"(g));
}
#define CP_COMMIT() asm volatile("cp.async.commit_group;")
#define CP_WAIT0()  asm volatile("cp.async.wait_group 0;")
#define CP_WAIT1()  asm volatile("cp.async.wait_group 1;")

__device__ __forceinline__ float ex2(float x) {
    float y;
    asm("ex2.approx.ftz.f32 %0, %1;" : "=f"(y) : "f"(x));
    return y;
}

__device__ __forceinline__ unsigned h2u(float a, float b) {
    __half2 h = __floats2half2_rn(a, b);
    return *(unsigned*)&h;
}

// ---------------------------------------------------------------------------
// fp32 -> fp16 bulk convert
// ---------------------------------------------------------------------------
__global__ __launch_bounds__(256)
void f2h_kernel(const float4* __restrict__ in, uint2* __restrict__ out, int n4)
{
    int i = blockIdx.x * blockDim.x + threadIdx.x;
    if (i < n4) {
        float4 a = in[i];
        out[i] = make_uint2(h2u(a.x, a.y), h2u(a.z, a.w));
    }
}

// ---------------------------------------------------------------------------
// RoPE cos/sin table
// ---------------------------------------------------------------------------
__global__ void rope_table_kernel()
{
    int i = blockIdx.x * blockDim.x + threadIdx.x;
    if (i < Tseq*32) {
        int tt = i >> 5, d = i & 31;
        float inv = 1.0f / powf(10000.0f, (float)d * (1.0f/32.0f));
        float ang = (float)tt * inv;
        g_cos[i] = cosf(ang);
        g_sin[i] = sinf(ang);
    }
}

// ---------------------------------------------------------------------------
// fp16 GEMM: C[M,N] = A[M,K]*B[N,K]^T, 128x128x32 tiles, 8 warps.
// cp.async 3-stage ring, ONE __syncthreads per k-chunk.  (round-12 proven)
// ROPE=true: fused RoPE + head-scatter epilogue -> g_qh/kh/vh.
// ---------------------------------------------------------------------------
#define GSTR 40   // halves per smem row
#define GEMM_SMEM (3 * 2 * 128 * GSTR * 2)   // 3 stages * (A+B) * 128 rows * 80B

template<bool ROPE>
__global__ __launch_bounds__(256)
void gemm_h(const __half* __restrict__ A, const __half* __restrict__ Bw,
            float* __restrict__ C, int M, int N, int K)
{
    extern __shared__ __half smem[];
    __half* As = smem;                    // 3 stages of 128*GSTR
    __half* Bs = smem + 3*128*GSTR;

    const int tid = threadIdx.x;
    const int lane = tid & 31;
    const int wid = tid >> 5;
    const int g = lane >> 2;
    const int t = lane & 3;
    const int wm = wid & 3;
    const int wn = wid >> 2;
    const int bm = blockIdx.y * 128;
    const int bn = blockIdx.x * 128;

    const int lr = tid >> 1;          // 0..127
    const int lc = (tid & 1) * 16;    // 0 or 16 halves
    const __half* Ap = A + (size_t)(bm + lr) * K + lc;
    const __half* Bp = Bw + (size_t)(bn + lr) * K + lc;

    const int a_row = (lane & 7) + ((lane & 8) ? 8 : 0);
    const int a_col = (lane & 16) ? 8 : 0;
    const int b_row = (lane & 7) + ((lane & 16) ? 8 : 0);
    const int b_col = (lane & 8) ? 8 : 0;

    float c[2][8][4] = {};

    // prologue: stages 0 and 1
    #pragma unroll
    for (int p = 0; p < 2; p++) {
        cp16(&As[p*128*GSTR + lr*GSTR + lc],     Ap + p*32);
        cp16(&As[p*128*GSTR + lr*GSTR + lc + 8], Ap + p*32 + 8);
        cp16(&Bs[p*128*GSTR + lr*GSTR + lc],     Bp + p*32);
        cp16(&Bs[p*128*GSTR + lr*GSTR + lc + 8], Bp + p*32 + 8);
        CP_COMMIT();
    }

    const int NK = K / 32;   // 32
    for (int ks = 0; ks < NK; ks++) {
        if (ks < NK - 1) { CP_WAIT1(); } else { CP_WAIT0(); }
        __syncthreads();
        // prefetch ks+2 (safe: its buffer was read at iter ks-1, all warps past)
        if (ks + 2 < NK) {
            int sb = (ks + 2) % 3;
            int k0 = (ks + 2) * 32;
            cp16(&As[sb*128*GSTR + lr*GSTR + lc],     Ap + k0);
            cp16(&As[sb*128*GSTR + lr*GSTR + lc + 8], Ap + k0 + 8);
            cp16(&Bs[sb*128*GSTR + lr*GSTR + lc],     Bp + k0);
            cp16(&Bs[sb*128*GSTR + lr*GSTR + lc + 8], Bp + k0 + 8);
            CP_COMMIT();
        }
        const __half* as = &As[(ks % 3)*128*GSTR];
        const __half* bs = &Bs[(ks % 3)*128*GSTR];
        #pragma unroll
        for (int kc = 0; kc < 2; kc++) {
            unsigned aF[2][4];
            #pragma unroll
            for (int m = 0; m < 2; m++)
                ldsm_x4(aF[m], &as[(wm*32 + m*16 + a_row)*GSTR + kc*16 + a_col]);
            #pragma unroll
            for (int jp = 0; jp < 4; jp++) {
                unsigned bF[4];
                ldsm_x4(bF, &bs[(wn*64 + jp*16 + b_row)*GSTR + kc*16 + b_col]);
                mma_f16(c[0][2*jp],   aF[0], bF[0], bF[1]);
                mma_f16(c[0][2*jp+1], aF[0], bF[2], bF[3]);
                mma_f16(c[1][2*jp],   aF[1], bF[0], bF[1]);
                mma_f16(c[1][2*jp+1], aF[1], bF[2], bF[3]);
            }
        }
    }

    if (!ROPE) {
        #pragma unroll
        for (int m = 0; m < 2; m++) {
            size_t r0 = (size_t)(bm + wm*32 + m*16 + g);
            #pragma unroll
            for (int j = 0; j < 8; j++) {
                int cc = bn + wn*64 + j*8 + t*2;
                *(float2*)&C[r0*N + cc]     = make_float2(c[m][j][0], c[m][j][1]);
                *(float2*)&C[(r0+8)*N + cc] = make_float2(c[m][j][2], c[m][j][3]);
            }
        }
    } else {
        // fused RoPE + scatter. Thread's cols j and j+4 are the (d, d+32) pair.
        const int colb = bn + wn*64;   // 64-aligned -> one head
        #pragma unroll
        for (int m = 0; m < 2; m++) {
            #pragma unroll
            for (int rr = 0; rr < 2; rr++) {
                int row = bm + wm*32 + m*16 + g + rr*8;
                int e0 = rr*2;
                int tpos = row & (Tseq-1);
                int bi = row >> 11;
                if (colb < TOTQ) {
                    int h = colb >> 6;
                    __half* q = g_qh + ((size_t)(bi*HQ + h)*Tseq + tpos)*HD;
                    #pragma unroll
                    for (int j = 0; j < 4; j++) {
                        int d = j*8 + t*2;
                        float2 cs = *(const float2*)&g_cos[tpos*32 + d];
                        float2 sn = *(const float2*)&g_sin[tpos*32 + d];
                        float v1x = c[m][j][e0],   v1y = c[m][j][e0+1];
                        float v2x = c[m][j+4][e0], v2y = c[m][j+4][e0+1];
                        *(unsigned*)&q[d] = h2u((v1x*cs.x - v2x*sn.x)*QSCALE,
                                                (v1y*cs.y - v2y*sn.y)*QSCALE);
                        *(unsigned*)&q[d+32] = h2u((v2x*cs.x + v1x*sn.x)*QSCALE,
                                                   (v2y*cs.y + v1y*sn.y)*QSCALE);
                    }
                } else if (colb < TOTQ + TOTKV) {
                    int h = (colb - TOTQ) >> 6;
                    __half* k = g_kh + ((size_t)(bi*HKV + h)*Tseq + tpos)*HD;
                    #pragma unroll
                    for (int j = 0; j < 4; j++) {
                        int d = j*8 + t*2;
                        float2 cs = *(const float2*)&g_cos[tpos*32 + d];
                        float2 sn = *(const float2*)&g_sin[tpos*32 + d];
                        float v1x = c[m][j][e0],   v1y = c[m][j][e0+1];
                        float v2x = c[m][j+4][e0], v2y = c[m][j+4][e0+1];
                        *(unsigned*)&k[d] = h2u(v1x*cs.x - v2x*sn.x,
                                                v1y*cs.y - v2y*sn.y);
                        *(unsigned*)&k[d+32] = h2u(v2x*cs.x + v1x*sn.x,
                                                   v2y*cs.y + v1y*sn.y);
                    }
                } else {
                    int h = (colb - TOTQ - TOTKV) >> 6;
                    __half* v = g_vh + ((size_t)(bi*HKV + h)*Tseq + tpos)*HD;
                    #pragma unroll
                    for (int j = 0; j < 8; j++) {
                        int d = j*8 + t*2;
                        *(unsigned*)&v[d] = h2u(c[m][j][e0], c[m][j][e0+1]);
                    }
                }
            }
        }
    }
}

// ---------------------------------------------------------------------------
// fp16 causal flash attention, KV shared across a 2-head half of the GQA group.
// Grid 1D, qt strictly descending: bid -> qt = 31 - bid/32; rem = bid%32 ->
// (b, hkv, hp). CTA = 256 threads / 8 warps: warp w -> head hkv*4 + hp*2 +
// (w&1), 16-row tile mt = w>>1. Two CTAs per (b,hkv,qt) -> 2 CTAs/SM resident
// (launch_bounds(256,2)); their softmax/mma phases interleave on the SM.
// cp.async 3-stage K/V ring, ONE __syncthreads per KV tile; log2 softmax.
// ---------------------------------------------------------------------------
#define KSTR 72     // halves per smem row
#define ATT_SMEM (3 * 2 * 64 * KSTR * 2)   // 55296 B; 2 CTAs = 108 KB/SM

__global__ __launch_bounds__(256, 2)
void attn_tc()
{
    extern __shared__ __half smem[];
    __half* Ks = smem;                  // 3 stages of 64*KSTR
    __half* Vs = smem + 3*64*KSTR;

    const int bid = blockIdx.x;
    const int qt  = (Tseq/64 - 1) - (bid >> 5);   // 31..0, descending
    const int rem = bid & 31;
    const int hp  = rem & 1;            // which 2-head half of the group
    const int hb  = rem >> 1;
    const int hkv = hb & 3;
    const int b   = hb >> 2;
    const int tid = threadIdx.x;
    const int lane = tid & 31;
    const int warp = tid >> 5;          // 0..7
    const int g = lane >> 2;
    const int t = lane & 3;
    const int h  = hkv*4 + hp*2 + (warp & 1);
    const int mt = warp >> 1;           // 0..3 -> 16-row tile within 64

    const int kb_row = (lane & 7) + ((lane & 16) ? 8 : 0);
    const int kb_col = (lane & 8) ? 8 : 0;
    const int vb_row = (lane & 7) + ((lane & 8) ? 8 : 0);
    const int vb_col = (lane & 16) ? 8 : 0;

    // Q fragments (half, pre-scaled by 0.125*log2e)
    const __half* Qg = g_qh + ((size_t)((b*HQ + h)*Tseq + qt*64 + mt*16))*HD;
    unsigned qa[4][4];
    #pragma unroll
    for (int kc = 0; kc < 4; kc++) {
        const __half* base = Qg + kc*16;
        qa[kc][0] = *(const unsigned*)&base[(g  )*HD + 2*t];
        qa[kc][1] = *(const unsigned*)&base[(g+8)*HD + 2*t];
        qa[kc][2] = *(const unsigned*)&base[(g  )*HD + 2*t + 8];
        qa[kc][3] = *(const unsigned*)&base[(g+8)*HD + 2*t + 8];
    }

    float o[8][4] = {};
    float mxA = -INFINITY, mxB = -INFINITY;
    float lsA = 0.f, lsB = 0.f;

    const __half* Kg0 = g_kh + ((size_t)(b*HKV + hkv)*Tseq)*HD;
    const __half* Vg0 = g_vh + ((size_t)(b*HKV + hkv)*Tseq)*HD;

    const int r  = tid >> 2;        // 0..63
    const int c0 = (tid & 3) * 16;  // halves (2 x 16B per thread per array)

    // prologue: stages 0 and (if present) 1
    cp16(&Ks[0*64*KSTR + r*KSTR + c0],     Kg0 + (size_t)r*HD + c0);
    cp16(&Ks[0*64*KSTR + r*KSTR + c0 + 8], Kg0 + (size_t)r*HD + c0 + 8);
    cp16(&Vs[0*64*KSTR + r*KSTR + c0],     Vg0 + (size_t)r*HD + c0);
    cp16(&Vs[0*64*KSTR + r*KSTR + c0 + 8], Vg0 + (size_t)r*HD + c0 + 8);
    CP_COMMIT();
    if (qt >= 1) {
        cp16(&Ks[1*64*KSTR + r*KSTR + c0],     Kg0 + (size_t)(64 + r)*HD + c0);
        cp16(&Ks[1*64*KSTR + r*KSTR + c0 + 8], Kg0 + (size_t)(64 + r)*HD + c0 + 8);
        cp16(&Vs[1*64*KSTR + r*KSTR + c0],     Vg0 + (size_t)(64 + r)*HD + c0);
        cp16(&Vs[1*64*KSTR + r*KSTR + c0 + 8], Vg0 + (size_t)(64 + r)*HD + c0 + 8);
        CP_COMMIT();
    }

    for (int j = 0; j <= qt; j++) {
        if (j < qt) { CP_WAIT1(); } else { CP_WAIT0(); }
        __syncthreads();
        // prefetch j+2 (its buffer was read at iter j-1; all warps past barrier)
        if (j + 2 <= qt) {
            int sb = (j + 2) % 3;
            const __half* kg = Kg0 + (size_t)((j+2)*64 + r)*HD + c0;
            const __half* vg = Vg0 + (size_t)((j+2)*64 + r)*HD + c0;
            cp16(&Ks[sb*64*KSTR + r*KSTR + c0],     kg);
            cp16(&Ks[sb*64*KSTR + r*KSTR + c0 + 8], kg + 8);
            cp16(&Vs[sb*64*KSTR + r*KSTR + c0],     vg);
            cp16(&Vs[sb*64*KSTR + r*KSTR + c0 + 8], vg + 8);
            CP_COMMIT();
        }
        const __half* ks = &Ks[(j % 3)*64*KSTR];
        const __half* vs = &Vs[(j % 3)*64*KSTR];

        // ---- S = Q*K^T (log2 domain) ----
        float s[8][4] = {};
        #pragma unroll
        for (int kc = 0; kc < 4; kc++) {
            #pragma unroll
            for (int jp = 0; jp < 4; jp++) {
                unsigned bF[4];
                ldsm_x4(bF, &ks[(jp*16 + kb_row)*KSTR + kc*16 + kb_col]);
                mma_f16(s[2*jp],   qa[kc], bF[0], bF[1]);
                mma_f16(s[2*jp+1], qa[kc], bF[2], bF[3]);
            }
        }

        if (j == qt) {   // causal mask within diagonal tile
            int rowA = mt*16 + g;   // local row within 64
            #pragma unroll
            for (int jn = 0; jn < 8; jn++) {
                #pragma unroll
                for (int e = 0; e < 2; e++) {
                    int col = jn*8 + t*2 + e;
                    if (col > rowA)     s[jn][e]   = -INFINITY;
                    if (col > rowA + 8) s[jn][2+e] = -INFINITY;
                }
            }
        }

        // ---- online softmax (base-2), rows g / g+8 ----
        float ma = -INFINITY, mb = -INFINITY;
        #pragma unroll
        for (int jn = 0; jn < 8; jn++) {
            ma = fmaxf(ma, fmaxf(s[jn][0], s[jn][1]));
            mb = fmaxf(mb, fmaxf(s[jn][2], s[jn][3]));
        }
        ma = fmaxf(ma, __shfl_xor_sync(0xffffffffu, ma, 1));
        ma = fmaxf(ma, __shfl_xor_sync(0xffffffffu, ma, 2));
        mb = fmaxf(mb, __shfl_xor_sync(0xffffffffu, mb, 1));
        mb = fmaxf(mb, __shfl_xor_sync(0xffffffffu, mb, 2));

        float mnA = fmaxf(mxA, ma), mnB = fmaxf(mxB, mb);
        float cA = ex2(mxA - mnA), cB = ex2(mxB - mnB);

        float la = 0.f, lb = 0.f;
        #pragma unroll
        for (int jn = 0; jn < 8; jn++) {
            s[jn][0] = ex2(s[jn][0] - mnA);
            s[jn][1] = ex2(s[jn][1] - mnA);
            s[jn][2] = ex2(s[jn][2] - mnB);
            s[jn][3] = ex2(s[jn][3] - mnB);
            la += s[jn][0] + s[jn][1];
            lb += s[jn][2] + s[jn][3];
        }
        la += __shfl_xor_sync(0xffffffffu, la, 1);
        la += __shfl_xor_sync(0xffffffffu, la, 2);
        lb += __shfl_xor_sync(0xffffffffu, lb, 1);
        lb += __shfl_xor_sync(0xffffffffu, lb, 2);
        lsA = lsA*cA + la;  mxA = mnA;
        lsB = lsB*cB + lb;  mxB = mnB;

        #pragma unroll
        for (int jd = 0; jd < 8; jd++) {
            o[jd][0] *= cA; o[jd][1] *= cA;
            o[jd][2] *= cB; o[jd][3] *= cB;
        }

        // pack P as fp16 A-fragments
        unsigned pa[4][4];
        #pragma unroll
        for (int kc = 0; kc < 4; kc++) {
            pa[kc][0] = h2u(s[2*kc][0],   s[2*kc][1]);
            pa[kc][1] = h2u(s[2*kc][2],   s[2*kc][3]);
            pa[kc][2] = h2u(s[2*kc+1][0], s[2*kc+1][1]);
            pa[kc][3] = h2u(s[2*kc+1][2], s[2*kc+1][3]);
        }

        // ---- O += P*V (V B-frags via ldmatrix.trans) ----
        #pragma unroll
        for (int kc = 0; kc < 4; kc++) {
            #pragma unroll
            for (int jp = 0; jp < 4; jp++) {
                unsigned bF[4];
                ldsm_x4_t(bF, &vs[(kc*16 + vb_row)*KSTR + jp*16 + vb_col]);
                mma_f16(o[2*jp],   pa[kc], bF[0], bF[1]);
                mma_f16(o[2*jp+1], pa[kc], bF[2], bF[3]);
            }
        }
    }

    // epilogue: normalize + store half
    const float invA = 1.f / lsA, invB = 1.f / lsB;
    size_t row0 = (size_t)(b*Tseq + qt*64 + mt*16 + g);
    __half* op = g_attnh + row0*TOTQ + h*HD;
    #pragma unroll
    for (int jd = 0; jd < 8; jd++) {
        int col = jd*8 + t*2;
        *(unsigned*)&op[col] = h2u(o[jd][0]*invA, o[jd][1]*invA);
        *(unsigned*)&op[(size_t)8*TOTQ + col] = h2u(o[jd][2]*invB, o[jd][3]*invB);
    }
}

// ---------------------------------------------------------------------------
extern "C" void kernel_launch(void* const* d_in, const int* in_sizes, int n_in,
                              void* d_out, int out_size)
{
    const float* x     = (const float*)d_in[0];
    const float* w_qkv = (const float*)d_in[1];
    const float* w_out = (const float*)d_in[2];
    float* out = (float*)d_out;

    __half *xh, *wqkvh, *wouth, *attnh;
    cudaGetSymbolAddress((void**)&xh, g_xh);
    cudaGetSymbolAddress((void**)&wqkvh, g_wqkvh);
    cudaGetSymbolAddress((void**)&wouth, g_wouth);
    cudaGetSymbolAddress((void**)&attnh, g_attnh);

    // idempotent host-side attribute sets (cheap; no static guards allowed)
    cudaFuncSetAttribute(gemm_h<true>,
        cudaFuncAttributeMaxDynamicSharedMemorySize, GEMM_SMEM);
    cudaFuncSetAttribute(gemm_h<false>,
        cudaFuncAttributeMaxDynamicSharedMemorySize, GEMM_SMEM);
    cudaFuncSetAttribute(attn_tc,
        cudaFuncAttributeMaxDynamicSharedMemorySize, ATT_SMEM);

    // 0) rope table + fp16 conversions
    rope_table_kernel<<<64, 1024>>>();
    f2h_kernel<<<(Mrows*Emb/4 + 255)/256, 256>>>((const float4*)x, (uint2*)xh, Mrows*Emb/4);
    f2h_kernel<<<(Fqkv*Emb/4 + 255)/256, 256>>>((const float4*)w_qkv, (uint2*)wqkvh, Fqkv*Emb/4);
    f2h_kernel<<<(TOTQ*Emb/4 + 255)/256, 256>>>((const float4*)w_out, (uint2*)wouth, TOTQ*Emb/4);

    // 1) QKV projection with fused RoPE + head scatter
    gemm_h<true><<<dim3(Fqkv/128, Mrows/128), 256, GEMM_SMEM>>>(xh, wqkvh, nullptr,
                                                                Mrows, Fqkv, Emb);
    // 2) causal GQA flash attention (2-head CTAs, 2 CTAs/SM, qt descending)
    attn_tc<<<(Tseq/64) * HKV * Bsz * 2, 256, ATT_SMEM>>>();

    // 3) output projection
    gemm_h<false><<<dim3(TOTQ/128, Mrows/128), 256, GEMM_SMEM>>>(attnh, wouth, out,
                                                                 Mrows, TOTQ, Emb);
}

// round 16
// speedup vs baseline: 1.0468x; 1.0468x over previous
#include <cuda_runtime.h>
#include <cuda_fp16.h>
#include <math.h>

#define Bsz 4
#define Tseq 2048
#define Emb 1024
#define HQ 16
#define HKV 4
#define HD 64
#define TOTQ (HQ*HD)            // 1024
#define TOTKV (HKV*HD)          // 256
#define Fqkv (TOTQ + 2*TOTKV)   // 1536
#define Mrows (Bsz*Tseq)        // 8192
#define QSCALE 0.1803368801111204f   // 0.125 * log2(e)

// Scratch (no allocations allowed -> __device__ globals)
__device__ __half g_xh[Mrows*Emb];
__device__ __half g_wqkvh[Fqkv*Emb];
__device__ __half g_wouth[TOTQ*Emb];
__device__ __half g_qh[Bsz*HQ*Tseq*HD];
__device__ __half g_kh[Bsz*HKV*Tseq*HD];
__device__ __half g_vh[Bsz*HKV*Tseq*HD];
__device__ __half g_attnh[Mrows * TOTQ];
__device__ float  g_cos[Tseq*32];
__device__ float  g_sin[Tseq*32];

// ---------------------------------------------------------------------------
// helpers
// ---------------------------------------------------------------------------
__device__ __forceinline__ void mma_f16(float* c, const unsigned* a,
                                        unsigned b0, unsigned b1) {
    asm volatile(
        "mma.sync.aligned.m16n8k16.row.col.f32.f16.f16.f32 "
        "{%0,%1,%2,%3}, {%4,%5,%6,%7}, {%8,%9}, {%0,%1,%2,%3};"
        : "+f"(c[0]), "+f"(c[1]), "+f"(c[2]), "+f"(c[3])
        : "r"(a[0]), "r"(a[1]), "r"(a[2]), "r"(a[3]), "r"(b0), "r"(b1));
}

__device__ __forceinline__ void ldsm_x4(unsigned* r, const void* p) {
    unsigned addr = (unsigned)__cvta_generic_to_shared(p);
    asm volatile("ldmatrix.sync.aligned.m8n8.x4.shared.b16 {%0,%1,%2,%3}, [%4];"
        : "=r"(r[0]), "=r"(r[1]), "=r"(r[2]), "=r"(r[3]) : "r"(addr));
}

__device__ __forceinline__ void ldsm_x4_t(unsigned* r, const void* p) {
    unsigned addr = (unsigned)__cvta_generic_to_shared(p);
    asm volatile("ldmatrix.sync.aligned.m8n8.x4.trans.shared.b16 {%0,%1,%2,%3}, [%4];"
        : "=r"(r[0]), "=r"(r[1]), "=r"(r[2]), "=r"(r[3]) : "r"(addr));
}

__device__ __forceinline__ void cp16(void* s, const void* g) {
    unsigned sa = (unsigned)__cvta_generic_to_shared(s);
    asm volatile("cp.async.cg.shared.global [%0], [%1], 16;" :: "r"(sa), "l"(g));
}
#define CP_COMMIT() asm volatile("cp.async.commit_group;")
#define CP_WAIT0()  asm volatile("cp.async.wait_group 0;")
#define CP_WAIT1()  asm volatile("cp.async.wait_group 1;")

__device__ __forceinline__ float ex2(float x) {
    float y;
    asm("ex2.approx.ftz.f32 %0, %1;" : "=f"(y) : "f"(x));
    return y;
}

__device__ __forceinline__ unsigned h2u(float a, float b) {
    __half2 h = __floats2half2_rn(a, b);
    return *(unsigned*)&h;
}

// ---------------------------------------------------------------------------
// fp32 -> fp16 bulk convert, all three tensors in ONE launch (segmented)
// ---------------------------------------------------------------------------
#define N4_X   (Mrows*Emb/4)           // 2097152
#define N4_WQ  (Fqkv*Emb/4)            // 393216
#define N4_WO  (TOTQ*Emb/4)            // 262144
#define N4_ALL (N4_X + N4_WQ + N4_WO)

__global__ __launch_bounds__(256)
void f2h_all_kernel(const float4* __restrict__ x,
                    const float4* __restrict__ wq,
                    const float4* __restrict__ wo)
{
    int i = blockIdx.x * blockDim.x + threadIdx.x;
    if (i >= N4_ALL) return;
    const float4* in;
    uint2* out;
    int k;
    if (i < N4_X) {
        in = x;  out = (uint2*)g_xh;    k = i;
    } else if (i < N4_X + N4_WQ) {
        in = wq; out = (uint2*)g_wqkvh; k = i - N4_X;
    } else {
        in = wo; out = (uint2*)g_wouth; k = i - N4_X - N4_WQ;
    }
    float4 a = in[k];
    out[k] = make_uint2(h2u(a.x, a.y), h2u(a.z, a.w));
}

// ---------------------------------------------------------------------------
// RoPE cos/sin table
// ---------------------------------------------------------------------------
__global__ void rope_table_kernel()
{
    int i = blockIdx.x * blockDim.x + threadIdx.x;
    if (i < Tseq*32) {
        int tt = i >> 5, d = i & 31;
        float inv = 1.0f / powf(10000.0f, (float)d * (1.0f/32.0f));
        float ang = (float)tt * inv;
        g_cos[i] = cosf(ang);
        g_sin[i] = sinf(ang);
    }
}

// ---------------------------------------------------------------------------
// fp16 GEMM: C[M,N] = A[M,K]*B[N,K]^T, 128x128x32 tiles, 8 warps.
// cp.async 3-stage ring, ONE __syncthreads per k-chunk.
// __launch_bounds__(256, 2): 2 CTAs/SM (regs<=128, smem 2x60KB fits).
// ROPE=true: fused RoPE + head-scatter epilogue -> g_qh/kh/vh.
// ---------------------------------------------------------------------------
#define GSTR 40   // halves per smem row
#define GEMM_SMEM (3 * 2 * 128 * GSTR * 2)   // 61440 B

template<bool ROPE>
__global__ __launch_bounds__(256, 2)
void gemm_h(const __half* __restrict__ A, const __half* __restrict__ Bw,
            float* __restrict__ C, int M, int N, int K)
{
    extern __shared__ __half smem[];
    __half* As = smem;                    // 3 stages of 128*GSTR
    __half* Bs = smem + 3*128*GSTR;

    const int tid = threadIdx.x;
    const int lane = tid & 31;
    const int wid = tid >> 5;
    const int g = lane >> 2;
    const int t = lane & 3;
    const int wm = wid & 3;
    const int wn = wid >> 2;
    const int bm = blockIdx.y * 128;
    const int bn = blockIdx.x * 128;

    const int lr = tid >> 1;          // 0..127
    const int lc = (tid & 1) * 16;    // 0 or 16 halves
    const __half* Ap = A + (size_t)(bm + lr) * K + lc;
    const __half* Bp = Bw + (size_t)(bn + lr) * K + lc;

    const int a_row = (lane & 7) + ((lane & 8) ? 8 : 0);
    const int a_col = (lane & 16) ? 8 : 0;
    const int b_row = (lane & 7) + ((lane & 16) ? 8 : 0);
    const int b_col = (lane & 8) ? 8 : 0;

    float c[2][8][4] = {};

    // prologue: stages 0 and 1
    #pragma unroll
    for (int p = 0; p < 2; p++) {
        cp16(&As[p*128*GSTR + lr*GSTR + lc],     Ap + p*32);
        cp16(&As[p*128*GSTR + lr*GSTR + lc + 8], Ap + p*32 + 8);
        cp16(&Bs[p*128*GSTR + lr*GSTR + lc],     Bp + p*32);
        cp16(&Bs[p*128*GSTR + lr*GSTR + lc + 8], Bp + p*32 + 8);
        CP_COMMIT();
    }

    const int NK = K / 32;   // 32
    for (int ks = 0; ks < NK; ks++) {
        if (ks < NK - 1) { CP_WAIT1(); } else { CP_WAIT0(); }
        __syncthreads();
        // prefetch ks+2 (safe: its buffer was read at iter ks-1, all warps past)
        if (ks + 2 < NK) {
            int sb = (ks + 2) % 3;
            int k0 = (ks + 2) * 32;
            cp16(&As[sb*128*GSTR + lr*GSTR + lc],     Ap + k0);
            cp16(&As[sb*128*GSTR + lr*GSTR + lc + 8], Ap + k0 + 8);
            cp16(&Bs[sb*128*GSTR + lr*GSTR + lc],     Bp + k0);
            cp16(&Bs[sb*128*GSTR + lr*GSTR + lc + 8], Bp + k0 + 8);
            CP_COMMIT();
        }
        const __half* as = &As[(ks % 3)*128*GSTR];
        const __half* bs = &Bs[(ks % 3)*128*GSTR];
        #pragma unroll
        for (int kc = 0; kc < 2; kc++) {
            unsigned aF[2][4];
            #pragma unroll
            for (int m = 0; m < 2; m++)
                ldsm_x4(aF[m], &as[(wm*32 + m*16 + a_row)*GSTR + kc*16 + a_col]);
            #pragma unroll
            for (int jp = 0; jp < 4; jp++) {
                unsigned bF[4];
                ldsm_x4(bF, &bs[(wn*64 + jp*16 + b_row)*GSTR + kc*16 + b_col]);
                mma_f16(c[0][2*jp],   aF[0], bF[0], bF[1]);
                mma_f16(c[0][2*jp+1], aF[0], bF[2], bF[3]);
                mma_f16(c[1][2*jp],   aF[1], bF[0], bF[1]);
                mma_f16(c[1][2*jp+1], aF[1], bF[2], bF[3]);
            }
        }
    }

    if (!ROPE) {
        #pragma unroll
        for (int m = 0; m < 2; m++) {
            size_t r0 = (size_t)(bm + wm*32 + m*16 + g);
            #pragma unroll
            for (int j = 0; j < 8; j++) {
                int cc = bn + wn*64 + j*8 + t*2;
                *(float2*)&C[r0*N + cc]     = make_float2(c[m][j][0], c[m][j][1]);
                *(float2*)&C[(r0+8)*N + cc] = make_float2(c[m][j][2], c[m][j][3]);
            }
        }
    } else {
        // fused RoPE + scatter. Thread's cols j and j+4 are the (d, d+32) pair.
        const int colb = bn + wn*64;   // 64-aligned -> one head
        #pragma unroll
        for (int m = 0; m < 2; m++) {
            #pragma unroll
            for (int rr = 0; rr < 2; rr++) {
                int row = bm + wm*32 + m*16 + g + rr*8;
                int e0 = rr*2;
                int tpos = row & (Tseq-1);
                int bi = row >> 11;
                if (colb < TOTQ) {
                    int h = colb >> 6;
                    __half* q = g_qh + ((size_t)(bi*HQ + h)*Tseq + tpos)*HD;
                    #pragma unroll
                    for (int j = 0; j < 4; j++) {
                        int d = j*8 + t*2;
                        float2 cs = *(const float2*)&g_cos[tpos*32 + d];
                        float2 sn = *(const float2*)&g_sin[tpos*32 + d];
                        float v1x = c[m][j][e0],   v1y = c[m][j][e0+1];
                        float v2x = c[m][j+4][e0], v2y = c[m][j+4][e0+1];
                        *(unsigned*)&q[d] = h2u((v1x*cs.x - v2x*sn.x)*QSCALE,
                                                (v1y*cs.y - v2y*sn.y)*QSCALE);
                        *(unsigned*)&q[d+32] = h2u((v2x*cs.x + v1x*sn.x)*QSCALE,
                                                   (v2y*cs.y + v1y*sn.y)*QSCALE);
                    }
                } else if (colb < TOTQ + TOTKV) {
                    int h = (colb - TOTQ) >> 6;
                    __half* k = g_kh + ((size_t)(bi*HKV + h)*Tseq + tpos)*HD;
                    #pragma unroll
                    for (int j = 0; j < 4; j++) {
                        int d = j*8 + t*2;
                        float2 cs = *(const float2*)&g_cos[tpos*32 + d];
                        float2 sn = *(const float2*)&g_sin[tpos*32 + d];
                        float v1x = c[m][j][e0],   v1y = c[m][j][e0+1];
                        float v2x = c[m][j+4][e0], v2y = c[m][j+4][e0+1];
                        *(unsigned*)&k[d] = h2u(v1x*cs.x - v2x*sn.x,
                                                v1y*cs.y - v2y*sn.y);
                        *(unsigned*)&k[d+32] = h2u(v2x*cs.x + v1x*sn.x,
                                                   v2y*cs.y + v1y*sn.y);
                    }
                } else {
                    int h = (colb - TOTQ - TOTKV) >> 6;
                    __half* v = g_vh + ((size_t)(bi*HKV + h)*Tseq + tpos)*HD;
                    #pragma unroll
                    for (int j = 0; j < 8; j++) {
                        int d = j*8 + t*2;
                        *(unsigned*)&v[d] = h2u(c[m][j][e0], c[m][j][e0+1]);
                    }
                }
            }
        }
    }
}

// ---------------------------------------------------------------------------
// fp16 causal flash attention (round-12 champion, unchanged).
// 1D grid qt-descending; 512 threads / 16 warps; cp.async 3-stage ring,
// one __syncthreads per KV tile; log2-domain softmax.
// ---------------------------------------------------------------------------
#define KSTR 72     // halves per smem row
#define ATT_SMEM (3 * 2 * 64 * KSTR * 2)

__global__ __launch_bounds__(512, 1)
void attn_tc()
{
    extern __shared__ __half smem[];
    __half* Ks = smem;
    __half* Vs = smem + 3*64*KSTR;

    const int bid = blockIdx.x;
    const int qt  = (Tseq/64 - 1) - (bid >> 4);
    const int hb  = bid & 15;
    const int hkv = hb & 3;
    const int b   = hb >> 2;
    const int tid = threadIdx.x;
    const int lane = tid & 31;
    const int warp = tid >> 5;
    const int g = lane >> 2;
    const int t = lane & 3;
    const int h  = hkv*4 + (warp & 3);
    const int mt = warp >> 2;

    const int kb_row = (lane & 7) + ((lane & 16) ? 8 : 0);
    const int kb_col = (lane & 8) ? 8 : 0;
    const int vb_row = (lane & 7) + ((lane & 8) ? 8 : 0);
    const int vb_col = (lane & 16) ? 8 : 0;

    const __half* Qg = g_qh + ((size_t)((b*HQ + h)*Tseq + qt*64 + mt*16))*HD;
    unsigned qa[4][4];
    #pragma unroll
    for (int kc = 0; kc < 4; kc++) {
        const __half* base = Qg + kc*16;
        qa[kc][0] = *(const unsigned*)&base[(g  )*HD + 2*t];
        qa[kc][1] = *(const unsigned*)&base[(g+8)*HD + 2*t];
        qa[kc][2] = *(const unsigned*)&base[(g  )*HD + 2*t + 8];
        qa[kc][3] = *(const unsigned*)&base[(g+8)*HD + 2*t + 8];
    }

    float o[8][4] = {};
    float mxA = -INFINITY, mxB = -INFINITY;
    float lsA = 0.f, lsB = 0.f;

    const __half* Kg0 = g_kh + ((size_t)(b*HKV + hkv)*Tseq)*HD;
    const __half* Vg0 = g_vh + ((size_t)(b*HKV + hkv)*Tseq)*HD;

    const int r  = tid >> 3;
    const int c0 = (tid & 7) * 8;

    cp16(&Ks[0*64*KSTR + r*KSTR + c0], Kg0 + (size_t)r*HD + c0);
    cp16(&Vs[0*64*KSTR + r*KSTR + c0], Vg0 + (size_t)r*HD + c0);
    CP_COMMIT();
    if (qt >= 1) {
        cp16(&Ks[1*64*KSTR + r*KSTR + c0], Kg0 + (size_t)(64 + r)*HD + c0);
        cp16(&Vs[1*64*KSTR + r*KSTR + c0], Vg0 + (size_t)(64 + r)*HD + c0);
        CP_COMMIT();
    }

    for (int j = 0; j <= qt; j++) {
        if (j < qt) { CP_WAIT1(); } else { CP_WAIT0(); }
        __syncthreads();
        if (j + 2 <= qt) {
            int sb = (j + 2) % 3;
            cp16(&Ks[sb*64*KSTR + r*KSTR + c0], Kg0 + (size_t)((j+2)*64 + r)*HD + c0);
            cp16(&Vs[sb*64*KSTR + r*KSTR + c0], Vg0 + (size_t)((j+2)*64 + r)*HD + c0);
            CP_COMMIT();
        }
        const __half* ks = &Ks[(j % 3)*64*KSTR];
        const __half* vs = &Vs[(j % 3)*64*KSTR];

        float s[8][4] = {};
        #pragma unroll
        for (int kc = 0; kc < 4; kc++) {
            #pragma unroll
            for (int jp = 0; jp < 4; jp++) {
                unsigned bF[4];
                ldsm_x4(bF, &ks[(jp*16 + kb_row)*KSTR + kc*16 + kb_col]);
                mma_f16(s[2*jp],   qa[kc], bF[0], bF[1]);
                mma_f16(s[2*jp+1], qa[kc], bF[2], bF[3]);
            }
        }

        if (j == qt) {
            int rowA = mt*16 + g;
            #pragma unroll
            for (int jn = 0; jn < 8; jn++) {
                #pragma unroll
                for (int e = 0; e < 2; e++) {
                    int col = jn*8 + t*2 + e;
                    if (col > rowA)     s[jn][e]   = -INFINITY;
                    if (col > rowA + 8) s[jn][2+e] = -INFINITY;
                }
            }
        }

        float ma = -INFINITY, mb = -INFINITY;
        #pragma unroll
        for (int jn = 0; jn < 8; jn++) {
            ma = fmaxf(ma, fmaxf(s[jn][0], s[jn][1]));
            mb = fmaxf(mb, fmaxf(s[jn][2], s[jn][3]));
        }
        ma = fmaxf(ma, __shfl_xor_sync(0xffffffffu, ma, 1));
        ma = fmaxf(ma, __shfl_xor_sync(0xffffffffu, ma, 2));
        mb = fmaxf(mb, __shfl_xor_sync(0xffffffffu, mb, 1));
        mb = fmaxf(mb, __shfl_xor_sync(0xffffffffu, mb, 2));

        float mnA = fmaxf(mxA, ma), mnB = fmaxf(mxB, mb);
        float cA = ex2(mxA - mnA), cB = ex2(mxB - mnB);

        float la = 0.f, lb = 0.f;
        #pragma unroll
        for (int jn = 0; jn < 8; jn++) {
            s[jn][0] = ex2(s[jn][0] - mnA);
            s[jn][1] = ex2(s[jn][1] - mnA);
            s[jn][2] = ex2(s[jn][2] - mnB);
            s[jn][3] = ex2(s[jn][3] - mnB);
            la += s[jn][0] + s[jn][1];
            lb += s[jn][2] + s[jn][3];
        }
        la += __shfl_xor_sync(0xffffffffu, la, 1);
        la += __shfl_xor_sync(0xffffffffu, la, 2);
        lb += __shfl_xor_sync(0xffffffffu, lb, 1);
        lb += __shfl_xor_sync(0xffffffffu, lb, 2);
        lsA = lsA*cA + la;  mxA = mnA;
        lsB = lsB*cB + lb;  mxB = mnB;

        #pragma unroll
        for (int jd = 0; jd < 8; jd++) {
            o[jd][0] *= cA; o[jd][1] *= cA;
            o[jd][2] *= cB; o[jd][3] *= cB;
        }

        unsigned pa[4][4];
        #pragma unroll
        for (int kc = 0; kc < 4; kc++) {
            pa[kc][0] = h2u(s[2*kc][0],   s[2*kc][1]);
            pa[kc][1] = h2u(s[2*kc][2],   s[2*kc][3]);
            pa[kc][2] = h2u(s[2*kc+1][0], s[2*kc+1][1]);
            pa[kc][3] = h2u(s[2*kc+1][2], s[2*kc+1][3]);
        }

        #pragma unroll
        for (int kc = 0; kc < 4; kc++) {
            #pragma unroll
            for (int jp = 0; jp < 4; jp++) {
                unsigned bF[4];
                ldsm_x4_t(bF, &vs[(kc*16 + vb_row)*KSTR + jp*16 + vb_col]);
                mma_f16(o[2*jp],   pa[kc], bF[0], bF[1]);
                mma_f16(o[2*jp+1], pa[kc], bF[2], bF[3]);
            }
        }
    }

    const float invA = 1.f / lsA, invB = 1.f / lsB;
    size_t row0 = (size_t)(b*Tseq + qt*64 + mt*16 + g);
    __half* op = g_attnh + row0*TOTQ + h*HD;
    #pragma unroll
    for (int jd = 0; jd < 8; jd++) {
        int col = jd*8 + t*2;
        *(unsigned*)&op[col] = h2u(o[jd][0]*invA, o[jd][1]*invA);
        *(unsigned*)&op[(size_t)8*TOTQ + col] = h2u(o[jd][2]*invB, o[jd][3]*invB);
    }
}

// ---------------------------------------------------------------------------
extern "C" void kernel_launch(void* const* d_in, const int* in_sizes, int n_in,
                              void* d_out, int out_size)
{
    const float* x     = (const float*)d_in[0];
    const float* w_qkv = (const float*)d_in[1];
    const float* w_out = (const float*)d_in[2];
    float* out = (float*)d_out;

    __half *xh, *wqkvh, *wouth, *attnh;
    cudaGetSymbolAddress((void**)&xh, g_xh);
    cudaGetSymbolAddress((void**)&wqkvh, g_wqkvh);
    cudaGetSymbolAddress((void**)&wouth, g_wouth);
    cudaGetSymbolAddress((void**)&attnh, g_attnh);

    // idempotent host-side attribute sets (cheap; no static guards allowed)
    cudaFuncSetAttribute(gemm_h<true>,
        cudaFuncAttributeMaxDynamicSharedMemorySize, GEMM_SMEM);
    cudaFuncSetAttribute(gemm_h<false>,
        cudaFuncAttributeMaxDynamicSharedMemorySize, GEMM_SMEM);
    cudaFuncSetAttribute(attn_tc,
        cudaFuncAttributeMaxDynamicSharedMemorySize, ATT_SMEM);

    // 0) rope table + fp16 conversions (single merged launch)
    rope_table_kernel<<<64, 1024>>>();
    f2h_all_kernel<<<(N4_ALL + 255)/256, 256>>>((const float4*)x,
                                                (const float4*)w_qkv,
                                                (const float4*)w_out);

    // 1) QKV projection with fused RoPE + head scatter (2 CTAs/SM)
    gemm_h<true><<<dim3(Fqkv/128, Mrows/128), 256, GEMM_SMEM>>>(xh, wqkvh, nullptr,
                                                                Mrows, Fqkv, Emb);
    // 2) causal GQA flash attention (round-12 config)
    attn_tc<<<(Tseq/64) * HKV * Bsz, 512, ATT_SMEM>>>();

    // 3) output projection (2 CTAs/SM)
    gemm_h<false><<<dim3(TOTQ/128, Mrows/128), 256, GEMM_SMEM>>>(attnh, wouth, out,
                                                                 Mrows, TOTQ, Emb);
}